// round 9
// baseline (speedup 1.0000x reference)
#include <cuda_runtime.h>
#include <cstddef>

// Problem constants
#define BV 32
#define CV 80
#define GV 128
#define GGV (GV * GV)     // 16384
#define NV 32
#define NBLK 128
#define NTHR 256
#define NWRP (NTHR / 32)  // 8 warps/block

// ---------------- scratch (device globals; no allocations) ----------------
__device__ float4 g_part[NBLK][2];  // 7 components + pad, as 2 float4s
__device__ int    g_sync = 0;       // reset by last block each run (graph-replay safe)

// ---------------- helpers ----------------
__device__ __forceinline__ float fsp(float x) {
    // softplus = max(x,0) + log(1 + exp(-|x|))  (matches jax.nn.softplus)
    return fmaxf(x, 0.0f) + __logf(1.0f + __expf(-fabsf(x)));
}

// ---------------- single fused kernel ----------------
// Decomposition: global warp gw = (b, j): b = batch, j = class-chunk.
// LANES = TARGETS. Each lane computes its own target's cell -> gathers
// cls[b, c, cell] for c in {j, j+32, j+64(j<16)} with NO pre-load shuffle.
// Dedup (match_any + ballots) overlaps the in-flight gathers.
__global__ void __launch_bounds__(NTHR) k_fused(const float* __restrict__ cls,
                                                const float* __restrict__ reg,
                                                const float* __restrict__ obj,
                                                const int*   __restrict__ tcl,
                                                const float* __restrict__ tbx,
                                                float* __restrict__ out) {
    float a0, a1 = 0.f, a2 = 0.f, a3 = 0.f, a4 = 0.f, a5 = 0.f, a6 = 0.f;

    const int tid  = blockIdx.x * NTHR + threadIdx.x;
    const int lane = threadIdx.x & 31;   // = target index n
    const int wid  = threadIdx.x >> 5;
    const int gw   = tid >> 5;           // global warp id: 0..1023
    const unsigned FULL = 0xffffffffu;

    const int b = gw >> 5;      // batch
    const int j = gw & 31;      // class chunk (c = j, j+32, j+64 when j<16)

    // ---- root of the dependent chain: this lane's own target row ----
    float4 tb = ((const float4*)tbx)[b * NV + lane];
    int    tc = tcl[b * NV + lane];

    // ---- independent dense obj loads (front-batched; overlap target round) ----
    const float4* o4 = (const float4*)obj;
    float4 v0 = o4[tid];
    float4 v1 = o4[tid + 1 * (NBLK * NTHR)];
    float4 v2 = o4[tid + 2 * (NBLK * NTHR)];
    float4 v3 = o4[tid + 3 * (NBLK * NTHR)];

    // ---- per-lane target geometry (no cross-lane dependency) ----
    float fx = tb.x * (float)GV, fy = tb.y * (float)GV;
    int gx = (int)floorf(fx);
    int gy = (int)floorf(fy);
    bool valid = (gx >= 0) && (gx < GV) && (gy >= 0) && (gy < GV);
    gx = min(max(gx, 0), GV - 1);
    gy = min(max(gy, 0), GV - 1);
    int cell = gy * GV + gx;             // always in-bounds (clamped)
    float one = valid ? 1.f : 0.f;
    float r0 = (fx - (float)gx) * one;   // reg_vals (zeroed when invalid)
    float r1 = (fy - (float)gy) * one;
    float r2 = sqrtf(tb.z) * one;
    float r3 = sqrtf(tb.w) * one;

    // ---- gathers issued IMMEDIATELY (addresses depend only on own lane) ----
    const float* base = cls + (size_t)b * CV * GGV + cell;
    float p0 = base[(size_t)j * GGV];
    float p1 = base[(size_t)(j + 32) * GGV];
    float p2 = (j < 16) ? base[(size_t)(j + 64) * GGV] : 0.f;
    float ov = (j == 0) ? obj[b * GGV + cell] : 0.f;
    float rg = (j < 4)  ? reg[(b * 4 + j) * GGV + cell] : 0.f;

    // ---- dedup machinery (executes while gathers are in flight) ----
    unsigned match    = __match_any_sync(FULL, cell);          // lanes sharing this cell (any validity)
    unsigned validbal = __ballot_sync(FULL, valid);
    unsigned matchVal = match & validbal;                      // valid lanes sharing this cell
    // representative: this lane is valid and is the FIRST valid lane with this cell
    bool rep = valid && ((matchVal & ((1u << lane) - 1u)) == 0u);
    // last writer of reg_target at this cell (any validity; .set semantics)
    int k_last = 31 - __clz((int)match);
    // class-set membership for warp-uniform classes c0/c1/c2
    unsigned s0 = __ballot_sync(FULL, valid && (tc == j));
    unsigned s1 = __ballot_sync(FULL, valid && (tc == j + 32));
    unsigned s2 = __ballot_sync(FULL, valid && (tc == j + 64)); // auto-0 for j>=16 (tc<80)
    // reg-target component j from the last writer of this lane's cell
    float rsel = (j == 0) ? r0 : (j == 1) ? r1 : (j == 2) ? r2 : r3;
    float rv = __shfl_sync(FULL, rsel, k_last);

    // ---- dense softplus compute (v0..v3 arrived during target round) ----
    {
        float lin = 0.f, prod = 1.f;
#pragma unroll
        for (int r = 0; r < 4; ++r) {
            float4 v = (r == 0) ? v0 : (r == 1) ? v1 : (r == 2) ? v2 : v3;
            lin += fmaxf(v.x, 0.f) + fmaxf(v.y, 0.f) + fmaxf(v.z, 0.f) + fmaxf(v.w, 0.f);
            prod *= (1.f + __expf(-fabsf(v.x)));   // each factor in (1,2]; <=16 factors, fp32-safe
            prod *= (1.f + __expf(-fabsf(v.y)));
            prod *= (1.f + __expf(-fabsf(v.z)));
            prod *= (1.f + __expf(-fabsf(v.w)));
        }
        a0 = lin + __logf(prod);
    }

    // ---- gather accumulation (predicated by rep; loads already landed) ----
    if (rep) {
        float clin = fmaxf(p0, 0.f) + fmaxf(p1, 0.f) + fmaxf(p2, 0.f);
        float cprod = (1.f + __expf(-fabsf(p0)))
                    * (1.f + __expf(-fabsf(p1)))
                    * ((j < 16) ? (1.f + __expf(-fabsf(p2))) : 1.f);
        a4 += clin + __logf(cprod);
        float ctgt = 0.f;
        if (s0 & match) ctgt += p0;            // class j in this cell's class set?
        if (s1 & match) ctgt += p1;
        if ((j < 16) && (s2 & match)) ctgt += p2;
        a5 += ctgt;
        if (j == 0) {
            a1 += ov;
            a2 += fsp(ov);
            a3 += 1.f;
        }
        if (j < 4) {
            float d = rg - rv;
            a6 += d * d;
        }
    }

    // ---- block reduction: warp shuffle -> smem -> warp0 ----
    __shared__ float sm[NWRP][8];
    __shared__ float totsm[8];
    __shared__ int   s_last;
    {
        float v[7] = {a0, a1, a2, a3, a4, a5, a6};
#pragma unroll
        for (int k = 0; k < 7; ++k) {
            float t = v[k];
#pragma unroll
            for (int o = 16; o; o >>= 1) t += __shfl_down_sync(FULL, t, o);
            if (lane == 0) sm[wid][k] = t;
        }
    }
    __syncthreads();
    if (wid == 0) {
        float t[7];
#pragma unroll
        for (int k = 0; k < 7; ++k) {
            float s = (lane < NWRP) ? sm[lane][k] : 0.f;
#pragma unroll
            for (int o = 4; o; o >>= 1) s += __shfl_down_sync(FULL, s, o);
            t[k] = s;
        }
        if (lane == 0) {
            g_part[blockIdx.x][0] = make_float4(t[0], t[1], t[2], t[3]);
            g_part[blockIdx.x][1] = make_float4(t[4], t[5], t[6], 0.f);
        }
    }
    // ---- last-block finalize (graph-replay-safe: counter self-resets) ----
    if (threadIdx.x == 0) {
        __threadfence();
        int t = atomicAdd(&g_sync, 1);
        s_last = (t == NBLK - 1) ? 1 : 0;
    }
    __syncthreads();
    if (s_last) {
        // warp k (k<7) reduces component k over all 128 block partials.
        if (wid < 7) {
            const float* gp = (const float*)g_part;
            float t = gp[lane * 8 + wid]
                    + gp[(lane + 32) * 8 + wid]
                    + gp[(lane + 64) * 8 + wid]
                    + gp[(lane + 96) * 8 + wid];
#pragma unroll
            for (int o = 16; o; o >>= 1) t += __shfl_down_sync(FULL, t, o);
            if (lane == 0) totsm[wid] = t;
        }
        __syncthreads();
        if (threadIdx.x == 0) {
            const double LN2 = 0.6931471805599453;
            double t0 = totsm[0], t1 = totsm[1], t2 = totsm[2], t3 = totsm[3];
            double t4 = totsm[4], t5 = totsm[5], t6 = totsm[6];
            double M     = t3;
            double obj_l = t0 - t1;
            double noobj = 0.5 * (t0 - t2 + M * LN2);
            double coord = 5.0 * t6;
            double cls_l = (double)CV * LN2 * ((double)(BV * GGV) - M) + t4 - t5;
            double total = obj_l + noobj + coord + cls_l;
            out[0] = (float)(total / (double)BV);
            out[1] = (float)(obj_l / (double)BV);
            out[2] = (float)(noobj / (double)BV);
            out[3] = (float)(coord / (double)BV);
            out[4] = (float)(cls_l / (double)BV);
            g_sync = 0;   // reset for next graph replay
        }
    }
}

// ---------------- launch ----------------
extern "C" void kernel_launch(void* const* d_in, const int* in_sizes, int n_in,
                              void* d_out, int out_size) {
    // Identify inputs by element count (all distinct) to be robust to ordering.
    const float* cls = nullptr;   // 32*80*128*128 = 41943040
    const float* reg = nullptr;   // 32*4*128*128  = 2097152
    const float* obj = nullptr;   // 32*1*128*128  = 524288
    const int*   tcl = nullptr;   // 32*32         = 1024
    const float* tbx = nullptr;   // 32*32*4       = 4096
    for (int i = 0; i < n_in; ++i) {
        switch (in_sizes[i]) {
            case 41943040: cls = (const float*)d_in[i]; break;
            case 2097152:  reg = (const float*)d_in[i]; break;
            case 524288:   obj = (const float*)d_in[i]; break;
            case 1024:     tcl = (const int*)d_in[i];   break;
            case 4096:     tbx = (const float*)d_in[i]; break;
            default: break;
        }
    }
    k_fused<<<NBLK, NTHR>>>(cls, reg, obj, tcl, tbx, (float*)d_out);
}

// round 10
// speedup vs baseline: 1.0118x; 1.0118x over previous
#include <cuda_runtime.h>
#include <cstddef>

// Problem constants
#define BV 32
#define CV 80
#define GV 128
#define GGV (GV * GV)     // 16384
#define NV 32
#define NBLK 128
#define NTHR 256
#define NWRP (NTHR / 32)  // 8 warps/block

// ---------------- scratch (device globals; no allocations) ----------------
__device__ float4 g_part[NBLK][2];  // 7 components + pad, as 2 float4s
__device__ int    g_sync = 0;       // reset by last block each run (graph-replay safe)

// ---------------- helpers ----------------
__device__ __forceinline__ float fsp(float x) {
    // softplus = max(x,0) + log(1 + exp(-|x|))  (matches jax.nn.softplus)
    return fmaxf(x, 0.0f) + __logf(1.0f + __expf(-fabsf(x)));
}

// ---------------- single fused kernel ----------------
// Decomposition: global warp gw = (b, j): b = batch, j = class-chunk.
// LANES = TARGETS. Each lane computes its own target's cell -> gathers
// cls[b, c, cell] for c in {j, j+32, j+64(j<16)} with NO pre-load shuffle.
// Dedup (match_any + ballots) overlaps the in-flight gathers.
__global__ void __launch_bounds__(NTHR) k_fused(const float* __restrict__ cls,
                                                const float* __restrict__ reg,
                                                const float* __restrict__ obj,
                                                const int*   __restrict__ tcl,
                                                const float* __restrict__ tbx,
                                                float* __restrict__ out) {
    float a0, a1 = 0.f, a2 = 0.f, a3 = 0.f, a4 = 0.f, a5 = 0.f, a6 = 0.f;

    const int tid  = blockIdx.x * NTHR + threadIdx.x;
    const int lane = threadIdx.x & 31;   // = target index n
    const int wid  = threadIdx.x >> 5;
    const int gw   = tid >> 5;           // global warp id: 0..1023
    const unsigned FULL = 0xffffffffu;

    const int b = gw >> 5;      // batch
    const int j = gw & 31;      // class chunk (c = j, j+32, j+64 when j<16)

    // ---- root of the dependent chain: this lane's own target row ----
    float4 tb = ((const float4*)tbx)[b * NV + lane];
    int    tc = tcl[b * NV + lane];

    // ---- independent dense obj loads (front-batched; overlap target round) ----
    const float4* o4 = (const float4*)obj;
    float4 v0 = o4[tid];
    float4 v1 = o4[tid + 1 * (NBLK * NTHR)];
    float4 v2 = o4[tid + 2 * (NBLK * NTHR)];
    float4 v3 = o4[tid + 3 * (NBLK * NTHR)];

    // ---- per-lane target geometry (no cross-lane dependency) ----
    float fx = tb.x * (float)GV, fy = tb.y * (float)GV;
    int gx = (int)floorf(fx);
    int gy = (int)floorf(fy);
    bool valid = (gx >= 0) && (gx < GV) && (gy >= 0) && (gy < GV);
    gx = min(max(gx, 0), GV - 1);
    gy = min(max(gy, 0), GV - 1);
    int cell = gy * GV + gx;             // always in-bounds (clamped)
    float one = valid ? 1.f : 0.f;
    float r0 = (fx - (float)gx) * one;   // reg_vals (zeroed when invalid)
    float r1 = (fy - (float)gy) * one;
    float r2 = sqrtf(tb.z) * one;
    float r3 = sqrtf(tb.w) * one;

    // ---- gathers issued IMMEDIATELY (addresses depend only on own lane) ----
    const float* base = cls + (size_t)b * CV * GGV + cell;
    float p0 = base[(size_t)j * GGV];
    float p1 = base[(size_t)(j + 32) * GGV];
    float p2 = (j < 16) ? base[(size_t)(j + 64) * GGV] : 0.f;
    float ov = (j == 0) ? obj[b * GGV + cell] : 0.f;
    float rg = (j < 4)  ? reg[(b * 4 + j) * GGV + cell] : 0.f;

    // ---- dedup machinery (executes while gathers are in flight) ----
    unsigned match    = __match_any_sync(FULL, cell);          // lanes sharing this cell (any validity)
    unsigned validbal = __ballot_sync(FULL, valid);
    unsigned matchVal = match & validbal;                      // valid lanes sharing this cell
    // representative: this lane is valid and is the FIRST valid lane with this cell
    bool rep = valid && ((matchVal & ((1u << lane) - 1u)) == 0u);
    // last writer of reg_target at this cell (any validity; .set semantics)
    int k_last = 31 - __clz((int)match);
    // class-set membership for warp-uniform classes c0/c1/c2
    unsigned s0 = __ballot_sync(FULL, valid && (tc == j));
    unsigned s1 = __ballot_sync(FULL, valid && (tc == j + 32));
    unsigned s2 = __ballot_sync(FULL, valid && (tc == j + 64)); // auto-0 for j>=16 (tc<80)
    // reg-target component j from the last writer of this lane's cell
    float rsel = (j == 0) ? r0 : (j == 1) ? r1 : (j == 2) ? r2 : r3;
    float rv = __shfl_sync(FULL, rsel, k_last);

    // ---- dense softplus compute (v0..v3 arrived during target round) ----
    {
        float lin = 0.f, prod = 1.f;
#pragma unroll
        for (int r = 0; r < 4; ++r) {
            float4 v = (r == 0) ? v0 : (r == 1) ? v1 : (r == 2) ? v2 : v3;
            lin += fmaxf(v.x, 0.f) + fmaxf(v.y, 0.f) + fmaxf(v.z, 0.f) + fmaxf(v.w, 0.f);
            prod *= (1.f + __expf(-fabsf(v.x)));   // each factor in (1,2]; <=16 factors, fp32-safe
            prod *= (1.f + __expf(-fabsf(v.y)));
            prod *= (1.f + __expf(-fabsf(v.z)));
            prod *= (1.f + __expf(-fabsf(v.w)));
        }
        a0 = lin + __logf(prod);
    }

    // ---- gather accumulation (predicated by rep; loads already landed) ----
    if (rep) {
        float clin = fmaxf(p0, 0.f) + fmaxf(p1, 0.f) + fmaxf(p2, 0.f);
        float cprod = (1.f + __expf(-fabsf(p0)))
                    * (1.f + __expf(-fabsf(p1)))
                    * ((j < 16) ? (1.f + __expf(-fabsf(p2))) : 1.f);
        a4 += clin + __logf(cprod);
        float ctgt = 0.f;
        if (s0 & match) ctgt += p0;            // class j in this cell's class set?
        if (s1 & match) ctgt += p1;
        if ((j < 16) && (s2 & match)) ctgt += p2;
        a5 += ctgt;
        if (j == 0) {
            a1 += ov;
            a2 += fsp(ov);
            a3 += 1.f;
        }
        if (j < 4) {
            float d = rg - rv;
            a6 += d * d;
        }
    }

    // ---- block reduction: warp shuffle -> smem -> warp0 ----
    __shared__ float sm[NWRP][8];
    __shared__ float totsm[8];
    __shared__ int   s_last;
    {
        float v[7] = {a0, a1, a2, a3, a4, a5, a6};
#pragma unroll
        for (int k = 0; k < 7; ++k) {
            float t = v[k];
#pragma unroll
            for (int o = 16; o; o >>= 1) t += __shfl_down_sync(FULL, t, o);
            if (lane == 0) sm[wid][k] = t;
        }
    }
    __syncthreads();
    if (wid == 0) {
        float t[7];
#pragma unroll
        for (int k = 0; k < 7; ++k) {
            float s = (lane < NWRP) ? sm[lane][k] : 0.f;
#pragma unroll
            for (int o = 4; o; o >>= 1) s += __shfl_down_sync(FULL, s, o);
            t[k] = s;
        }
        if (lane == 0) {
            g_part[blockIdx.x][0] = make_float4(t[0], t[1], t[2], t[3]);
            g_part[blockIdx.x][1] = make_float4(t[4], t[5], t[6], 0.f);
        }
    }
    // ---- last-block finalize (graph-replay-safe: counter self-resets) ----
    if (threadIdx.x == 0) {
        __threadfence();
        int t = atomicAdd(&g_sync, 1);
        s_last = (t == NBLK - 1) ? 1 : 0;
    }
    __syncthreads();
    if (s_last) {
        // warp k (k<7) reduces component k over all 128 block partials.
        if (wid < 7) {
            const float* gp = (const float*)g_part;
            float t = gp[lane * 8 + wid]
                    + gp[(lane + 32) * 8 + wid]
                    + gp[(lane + 64) * 8 + wid]
                    + gp[(lane + 96) * 8 + wid];
#pragma unroll
            for (int o = 16; o; o >>= 1) t += __shfl_down_sync(FULL, t, o);
            if (lane == 0) totsm[wid] = t;
        }
        __syncthreads();
        if (threadIdx.x == 0) {
            const double LN2 = 0.6931471805599453;
            double t0 = totsm[0], t1 = totsm[1], t2 = totsm[2], t3 = totsm[3];
            double t4 = totsm[4], t5 = totsm[5], t6 = totsm[6];
            double M     = t3;
            double obj_l = t0 - t1;
            double noobj = 0.5 * (t0 - t2 + M * LN2);
            double coord = 5.0 * t6;
            double cls_l = (double)CV * LN2 * ((double)(BV * GGV) - M) + t4 - t5;
            double total = obj_l + noobj + coord + cls_l;
            out[0] = (float)(total / (double)BV);
            out[1] = (float)(obj_l / (double)BV);
            out[2] = (float)(noobj / (double)BV);
            out[3] = (float)(coord / (double)BV);
            out[4] = (float)(cls_l / (double)BV);
            g_sync = 0;   // reset for next graph replay
        }
    }
}

// ---------------- launch ----------------
extern "C" void kernel_launch(void* const* d_in, const int* in_sizes, int n_in,
                              void* d_out, int out_size) {
    // Identify inputs by element count (all distinct) to be robust to ordering.
    const float* cls = nullptr;   // 32*80*128*128 = 41943040
    const float* reg = nullptr;   // 32*4*128*128  = 2097152
    const float* obj = nullptr;   // 32*1*128*128  = 524288
    const int*   tcl = nullptr;   // 32*32         = 1024
    const float* tbx = nullptr;   // 32*32*4       = 4096
    for (int i = 0; i < n_in; ++i) {
        switch (in_sizes[i]) {
            case 41943040: cls = (const float*)d_in[i]; break;
            case 2097152:  reg = (const float*)d_in[i]; break;
            case 524288:   obj = (const float*)d_in[i]; break;
            case 1024:     tcl = (const int*)d_in[i];   break;
            case 4096:     tbx = (const float*)d_in[i]; break;
            default: break;
        }
    }
    k_fused<<<NBLK, NTHR>>>(cls, reg, obj, tcl, tbx, (float*)d_out);
}